// round 16
// baseline (speedup 1.0000x reference)
#include <cuda_runtime.h>
#include <cstdint>

// Shapes (fixed):
//   x:   [B=8, 37, 37, 384] fp32, channel-last
//   out: [B, 29*384, 37, 37] fp32; out(b,bin,c,y,x) at ((b*29+bin)*384 + c)*1369 + y*37 + x
//   bins 0..8 : raw shifted by (dy,dx) in {-1,0,1}^2 (row-major), border-clamped
//   bins 9..16: 3x3 avgpool (count_include_pad=False) shifted (dy,dx) in {-3,0,3}^2 \ {0,0}
//   bins 17..28: zeros

#define BATCH 8
#define W 37
#define D 384
#define NBINS 29
#define PLANE (W * W)                    // 1369
#define CHPLANE ((size_t)D * PLANE)      // 525696
#define G 2                              // channels per gather block

#define PADW 44                          // padded row stride; logical x,y in [-3, 39]
#define PADH 43
#define PSZ (PADH * PADW)                // 1892
#define SWZ(j) ((j) + ((j) >> 5))        // stride-4 lane access -> conflict-free
#define SPSZ (PSZ + (PSZ >> 5) + 4)      // 1955

#define NGATHER ((D / G) * BATCH)        // 1536
#define NZERO   768
#define NBLOCKS (NGATHER + NZERO)        // 2304; every 3rd block (bx%3==2) is a zero block

#define ZPB    96                        // zero blocks per batch
#define ZCHUNK 16428                     // float4s per zero block (12*CHPLANE/4 / 96, exact)

__device__ __forceinline__ int clampw(int v) { return min(max(v, 0), W - 1); }

// Padded-plane index for logical (y, x) with y,x possibly in [-3, W+2].
#define PIDX(y, x) (((y) + 3) * PADW + ((x) + 3))

__device__ __constant__ int c_off[17] = {
    -PADW - 1, -PADW, -PADW + 1,  -1, 0, 1,  PADW - 1, PADW, PADW + 1,
    -3 * PADW - 3, -3 * PADW, -3 * PADW + 3,  -3, 3,  3 * PADW - 3, 3 * PADW, 3 * PADW + 3
};

__global__ __launch_bounds__(256) void fanout_kernel(const float* __restrict__ in,
                                                     float* __restrict__ out) {
    const int bx  = blockIdx.x;
    const int tid = threadIdx.x;

    // ------------- Zero blocks: contiguous float4 fill of bins 17..28 -------------
    if (bx % 3 == 2) {
        const int zid = bx / 3;
        const int zb  = zid / ZPB;
        const int p   = zid - zb * ZPB;
        const size_t plane4 = CHPLANE / 4;
        float4* dst = reinterpret_cast<float4*>(out) +
                      ((size_t)zb * NBINS + 17) * plane4 + (size_t)p * ZCHUNK;
        const float4 z = make_float4(0.f, 0.f, 0.f, 0.f);
        for (int k = tid; k < ZCHUNK; k += 256)
            dst[k] = z;
        return;
    }

    // ---------------- Gather blocks ----------------
    const int gidx = bx - bx / 3;                      // 0..NGATHER-1
    const int c0 = (gidx % (D / G)) * G;
    const int b  = gidx / (D / G);

    __shared__ float sr[G][SPSZ];   // padded pre-clamped raw planes (swizzled)
    __shared__ float sp[G][SPSZ];   // padded pre-clamped pooled planes (swizzled)

    // Load interior: 2 channels per spatial element with one float2 LDG.
    const float2* src2 = reinterpret_cast<const float2*>(in + (size_t)b * PLANE * D + c0);
    for (int i = tid; i < PLANE; i += 256) {
        int y = i / W, x = i - y * W;
        float2 v = src2[(size_t)i * (D / 2)];
        int js = SWZ(PIDX(y, x));
        sr[0][js] = v.x; sr[1][js] = v.y;
    }
    __syncthreads();

    // Border-fill raw planes + 3x3 pool interior.
    for (int t = tid; t < G * PSZ; t += 256) {
        int g = t / PSZ, j = t - g * PSZ;
        int py = j / PADW, px = j - py * PADW;
        if (px > PADH - 1) continue;                   // col 43 unused
        int y = py - 3, x = px - 3;
        if ((unsigned)y < (unsigned)W && (unsigned)x < (unsigned)W) continue;
        sr[g][SWZ(j)] = sr[g][SWZ(PIDX(clampw(y), clampw(x)))];
    }
    for (int t = tid; t < G * PLANE; t += 256) {
        int g = t / PLANE, i = t - g * PLANE;
        int y = i / W, x = i - y * W;
        int y0 = max(y - 1, 0), y1 = min(y + 1, W - 1);
        int x0 = max(x - 1, 0), x1 = min(x + 1, W - 1);
        float s = 0.f;
        for (int yy = y0; yy <= y1; yy++)
            for (int xx = x0; xx <= x1; xx++)
                s += sr[g][SWZ(PIDX(yy, xx))];
        sp[g][SWZ(PIDX(y, x))] = s * (1.0f / (float)((y1 - y0 + 1) * (x1 - x0 + 1)));
    }
    __syncthreads();

    // Border-fill pooled planes.
    for (int t = tid; t < G * PSZ; t += 256) {
        int g = t / PSZ, j = t - g * PSZ;
        int py = j / PADW, px = j - py * PADW;
        if (px > PADH - 1) continue;
        int y = py - 3, x = px - 3;
        if ((unsigned)y < (unsigned)W && (unsigned)x < (unsigned)W) continue;
        sp[g][SWZ(j)] = sp[g][SWZ(PIDX(clampw(y), clampw(x)))];
    }
    __syncthreads();

    // ---- Gather + store 17 bins per channel, row-aligned quads with window reuse ----
    #pragma unroll 1
    for (int g = 0; g < G; g++) {
        const float* __restrict__ a_r = sr[g];
        const float* __restrict__ a_p = sp[g];
        const int c = c0 + g;

        const size_t ob = ((size_t)(b * NBINS) * D + c) * PLANE;
        float* const obase = out + ob;                 // ob % 4 == c % 4

        // Quad pass: slots (row r, s in [0,9)); x0 = p_r + 4s, row-aligned 16B quads.
        for (int t = tid; t < W * 9; t += 256) {
            int r = t / 9, s = t - r * 9;
            int p = (4 - ((c + r) & 3)) & 3;           // 37 == 1 (mod 4)
            int x0 = p + 4 * s;
            if (x0 > W - 4) continue;                  // leftover pass handles the rest
            float* const orow = obase + r * W + x0;    // 16B aligned by construction

            // Raw bins: rows dy=-1,0,1; window cols x0-1 .. x0+4 (6 floats).
            #pragma unroll
            for (int dyi = 0; dyi < 3; dyi++) {
                int jb = (r + dyi + 2) * PADW + (x0 + 2);  // PIDX(r+dy, x0-1)
                float w0 = a_r[SWZ(jb)],     w1 = a_r[SWZ(jb + 1)];
                float w2 = a_r[SWZ(jb + 2)], w3 = a_r[SWZ(jb + 3)];
                float w4 = a_r[SWZ(jb + 4)], w5 = a_r[SWZ(jb + 5)];
                *reinterpret_cast<float4*>(orow + (size_t)(dyi * 3 + 0) * CHPLANE) =
                    make_float4(w0, w1, w2, w3);
                *reinterpret_cast<float4*>(orow + (size_t)(dyi * 3 + 1) * CHPLANE) =
                    make_float4(w1, w2, w3, w4);
                *reinterpret_cast<float4*>(orow + (size_t)(dyi * 3 + 2) * CHPLANE) =
                    make_float4(w2, w3, w4, w5);
            }

            // Pooled bins: rows dy=-3,0,3; window cols x0-3 .. x0+6 (10 floats).
            {
                // dy = -3 : bins 9,10,11
                int jb = (r + 0) * PADW + x0;              // PIDX(r-3, x0-3)
                float w0 = a_p[SWZ(jb)],     w1 = a_p[SWZ(jb + 1)];
                float w2 = a_p[SWZ(jb + 2)], w3 = a_p[SWZ(jb + 3)];
                float w4 = a_p[SWZ(jb + 4)], w5 = a_p[SWZ(jb + 5)];
                float w6 = a_p[SWZ(jb + 6)], w7 = a_p[SWZ(jb + 7)];
                float w8 = a_p[SWZ(jb + 8)], w9 = a_p[SWZ(jb + 9)];
                *reinterpret_cast<float4*>(orow + (size_t) 9 * CHPLANE) = make_float4(w0, w1, w2, w3);
                *reinterpret_cast<float4*>(orow + (size_t)10 * CHPLANE) = make_float4(w3, w4, w5, w6);
                *reinterpret_cast<float4*>(orow + (size_t)11 * CHPLANE) = make_float4(w6, w7, w8, w9);
            }
            {
                // dy = 0 : bins 12 (dx=-3), 13 (dx=+3); center skipped
                int jb = (r + 3) * PADW + x0;              // PIDX(r, x0-3)
                float w0 = a_p[SWZ(jb)],     w1 = a_p[SWZ(jb + 1)];
                float w2 = a_p[SWZ(jb + 2)], w3 = a_p[SWZ(jb + 3)];
                float w6 = a_p[SWZ(jb + 6)], w7 = a_p[SWZ(jb + 7)];
                float w8 = a_p[SWZ(jb + 8)], w9 = a_p[SWZ(jb + 9)];
                *reinterpret_cast<float4*>(orow + (size_t)12 * CHPLANE) = make_float4(w0, w1, w2, w3);
                *reinterpret_cast<float4*>(orow + (size_t)13 * CHPLANE) = make_float4(w6, w7, w8, w9);
            }
            {
                // dy = +3 : bins 14,15,16
                int jb = (r + 6) * PADW + x0;              // PIDX(r+3, x0-3)
                float w0 = a_p[SWZ(jb)],     w1 = a_p[SWZ(jb + 1)];
                float w2 = a_p[SWZ(jb + 2)], w3 = a_p[SWZ(jb + 3)];
                float w4 = a_p[SWZ(jb + 4)], w5 = a_p[SWZ(jb + 5)];
                float w6 = a_p[SWZ(jb + 6)], w7 = a_p[SWZ(jb + 7)];
                float w8 = a_p[SWZ(jb + 8)], w9 = a_p[SWZ(jb + 9)];
                *reinterpret_cast<float4*>(orow + (size_t)14 * CHPLANE) = make_float4(w0, w1, w2, w3);
                *reinterpret_cast<float4*>(orow + (size_t)15 * CHPLANE) = make_float4(w3, w4, w5, w6);
                *reinterpret_cast<float4*>(orow + (size_t)16 * CHPLANE) = make_float4(w6, w7, w8, w9);
            }
        }

        // Leftover scalars: per row, head (p) + tail ((W-p)&3) elements.
        for (int t = tid; t < W * 5; t += 256) {
            int r = t / 5, j = t - r * 5;
            int p = (4 - ((c + r) & 3)) & 3;
            int nqr = (W - p) >> 2, tl = (W - p) & 3;
            int x;
            if (j < p) x = j;
            else { int jj = j - p; if (jj >= tl) continue; x = p + 4 * nqr + jj; }

            int base = PIDX(r, x);
            float* const oel = obase + r * W + x;
            #pragma unroll
            for (int bin = 0; bin < 17; bin++) {
                const float* a = (bin < 9) ? a_r : a_p;
                oel[(size_t)bin * CHPLANE] = a[SWZ(base + c_off[bin])];
            }
        }
    }
}

// ---------------------------------------------------------------------------
extern "C" void kernel_launch(void* const* d_in, const int* in_sizes, int n_in,
                              void* d_out, int out_size) {
    const float* x = (const float*)d_in[0];
    float* out = (float*)d_out;
    fanout_kernel<<<NBLOCKS, 256>>>(x, out);
}

// round 17
// speedup vs baseline: 1.4248x; 1.4248x over previous
#include <cuda_runtime.h>
#include <cstdint>

// Shapes (fixed):
//   x:   [B=8, 37, 37, 384] fp32, channel-last
//   out: [B, 29*384, 37, 37] fp32; out(b,bin,c,y,x) at ((b*29+bin)*384 + c)*1369 + y*37 + x
//   bins 0..8 : raw shifted by (dy,dx) in {-1,0,1}^2 (row-major), border-clamped
//   bins 9..16: 3x3 avgpool (count_include_pad=False) shifted (dy,dx) in {-3,0,3}^2 \ {0,0}
//   bins 17..28: zeros

#define BATCH 8
#define W 37
#define D 384
#define NBINS 29
#define PLANE (W * W)                    // 1369
#define CHPLANE ((size_t)D * PLANE)      // 525696
#define G 2                              // channels per block
#define NT 384                           // threads per block

#define PADW 44                          // padded row stride; logical x,y in [-3, 39]
#define PADH 43
#define PSZ (PADH * PADW)                // 1892
#define SWZ(j) ((j) + ((j) >> 5))        // stride-4 lane access -> conflict-free
#define SPSZ (PSZ + (PSZ >> 5) + 4)      // 1955

#define NBORD 480                        // border cells per padded plane (6*43 + 37*6)

__device__ __forceinline__ int clampw(int v) { return min(max(v, 0), W - 1); }

// Padded-plane index for logical (y, x) with y,x possibly in [-3, W+2].
#define PIDX(y, x) (((y) + 3) * PADW + ((x) + 3))

__device__ __constant__ int c_off[17] = {
    -PADW - 1, -PADW, -PADW + 1,  -1, 0, 1,  PADW - 1, PADW, PADW + 1,
    -3 * PADW - 3, -3 * PADW, -3 * PADW + 3,  -3, 3,  3 * PADW - 3, 3 * PADW, 3 * PADW + 3
};
__device__ __constant__ int c_bedge[6] = { 0, 1, 2, 40, 41, 42 };

// Map border-cell index idx in [0, NBORD) -> padded (py, px).
__device__ __forceinline__ void border_cell(int idx, int& py, int& px) {
    if (idx < 258) {                       // 6 full border rows x 43 cols
        int r = idx / 43;                  // const div
        py = c_bedge[r];
        px = idx - r * 43;
    } else {                               // 37 interior rows x 6 border cols
        int k = idx - 258;
        int r = k / 6;                     // const div
        py = 3 + r;
        px = c_bedge[k - r * 6];
    }
}

__global__ __launch_bounds__(NT) void fanout_kernel(const float* __restrict__ in,
                                                    float* __restrict__ out) {
    const int gidx = blockIdx.x;                       // 0..(D/G)*BATCH-1
    const int c0 = (gidx % (D / G)) * G;
    const int b  = gidx / (D / G);
    const int tid = threadIdx.x;

    __shared__ float sr[G][SPSZ];   // padded pre-clamped raw planes (swizzled)
    __shared__ float sp[G][SPSZ];   // padded pre-clamped pooled planes (swizzled)

    // ---- Phase 0a: issue interior loads (latency-bound) ----
    const float2* src2 = reinterpret_cast<const float2*>(in + (size_t)b * PLANE * D + c0);
    for (int i = tid; i < PLANE; i += NT) {
        int y = i / W, x = i - y * W;
        float2 v = src2[(size_t)i * (D / 2)];
        int js = SWZ(PIDX(y, x));
        sr[0][js] = v.x; sr[1][js] = v.y;
    }

    // ---- Phase 0b: dependency-free zero stores for bins 17..28 (both channels).
    //      These drain while the loads above are in flight and while the pool
    //      phases below run — the block overlaps its own prologue. ----
    #pragma unroll 1
    for (int g = 0; g < G; g++) {
        const int c = c0 + g;
        const size_t ob = ((size_t)(b * NBINS) * D + c) * PLANE;
        float* const obase = out + ob;
        const int head = (4 - (c & 3)) & 3;
        const int nq   = (PLANE - head) >> 2;
        const int tail = (PLANE - head) & 3;
        if (tid < nq) {
            const int i0 = head + 4 * tid;
            const float4 z = make_float4(0.f, 0.f, 0.f, 0.f);
            #pragma unroll
            for (int bin = 17; bin < NBINS; bin++)
                *reinterpret_cast<float4*>(obase + (size_t)bin * CHPLANE + i0) = z;
        } else if (tid < nq + head + tail) {
            int k = tid - nq;
            int si = (k < head) ? k : (head + 4 * nq + (k - head));
            #pragma unroll
            for (int bin = 17; bin < NBINS; bin++)
                obase[(size_t)bin * CHPLANE + si] = 0.f;
        }
    }
    __syncthreads();

    // ---- Phase 1: raw border fill (compact mapping) + 3x3 pool interior ----
    for (int t = tid; t < G * NBORD; t += NT) {
        int g = t >= NBORD;
        int idx = t - g * NBORD;
        int py, px; border_cell(idx, py, px);
        sr[g][SWZ(py * PADW + px)] = sr[g][SWZ(PIDX(clampw(py - 3), clampw(px - 3)))];
    }
    for (int t = tid; t < G * PLANE; t += NT) {
        int g = t / PLANE, i = t - g * PLANE;
        int y = i / W, x = i - y * W;
        int y0 = max(y - 1, 0), y1 = min(y + 1, W - 1);
        int x0 = max(x - 1, 0), x1 = min(x + 1, W - 1);
        float s = 0.f;
        for (int yy = y0; yy <= y1; yy++)
            for (int xx = x0; xx <= x1; xx++)
                s += sr[g][SWZ(PIDX(yy, xx))];
        sp[g][SWZ(PIDX(y, x))] = s * (1.0f / (float)((y1 - y0 + 1) * (x1 - x0 + 1)));
    }
    __syncthreads();

    // ---- Phase 2: pooled border fill (compact mapping) ----
    for (int t = tid; t < G * NBORD; t += NT) {
        int g = t >= NBORD;
        int idx = t - g * NBORD;
        int py, px; border_cell(idx, py, px);
        sp[g][SWZ(py * PADW + px)] = sp[g][SWZ(PIDX(clampw(py - 3), clampw(px - 3)))];
    }
    __syncthreads();

    // ---- Phase 3: gather + store 17 bins per channel (R15 body, single sweep) ----
    #pragma unroll 1
    for (int g = 0; g < G; g++) {
        const float* __restrict__ a_r = sr[g];
        const float* __restrict__ a_p = sp[g];

        const size_t ob = ((size_t)(b * NBINS) * D + (c0 + g)) * PLANE;
        float* const obase = out + ob;
        const int head = (4 - ((c0 + g) & 3)) & 3;     // ob % 4 == c % 4
        const int nq   = (PLANE - head) >> 2;
        const int tail = (PLANE - head) & 3;

        if (tid < nq) {
            const int i0 = head + 4 * tid;
            int y0 = i0 / W, x0 = i0 - y0 * W;
            int be[4];
            #pragma unroll
            for (int e = 0; e < 4; e++) {
                int xi = x0 + e, yi = y0;
                if (xi >= W) { xi -= W; yi++; }        // at most one row crossing
                be[e] = PIDX(yi, xi);
            }

            #pragma unroll
            for (int bin = 0; bin < 17; bin++) {
                const float* a = (bin < 9) ? a_r : a_p;
                const int off = c_off[bin];
                float4 r;
                r.x = a[SWZ(be[0] + off)];
                r.y = a[SWZ(be[1] + off)];
                r.z = a[SWZ(be[2] + off)];
                r.w = a[SWZ(be[3] + off)];
                *reinterpret_cast<float4*>(obase + (size_t)bin * CHPLANE + i0) = r;
            }
        } else if (tid < nq + head + tail) {
            int k = tid - nq;
            int si = (k < head) ? k : (head + 4 * nq + (k - head));
            int y = si / W, x = si - y * W;
            int base = PIDX(y, x);
            #pragma unroll
            for (int bin = 0; bin < 17; bin++) {
                const float* a = (bin < 9) ? a_r : a_p;
                obase[(size_t)bin * CHPLANE + si] = a[SWZ(base + c_off[bin])];
            }
        }
    }
}

// ---------------------------------------------------------------------------
extern "C" void kernel_launch(void* const* d_in, const int* in_sizes, int n_in,
                              void* d_out, int out_size) {
    const float* x = (const float*)d_in[0];
    float* out = (float*)d_out;
    fanout_kernel<<<(D / G) * BATCH, NT>>>(x, out);    // 1536 blocks
}